// round 15
// baseline (speedup 1.0000x reference)
#include <cuda_runtime.h>

// Retrace: B=2048, T=512, D=16 (fp32). Single persistent kernel.
// Phase 1: warp-cooperative cp.async-staged segmented affine scan.
//   Each warp owns 32 chains (2 b-rows x 16 d) over one 128-step segment.
//   Per 4-step chunk: 5 arrays arrive as dense 512B warp requests via
//   cp.async.cg (L1-bypass), BPP via cp.async.ca 4B.
//   THREE SMEM stages, layout [array][t][b*d] (conflict-free, zero padding)
//   -> issue runs ~3 chunk-cycles ahead of the wait -> DRAM latency hidden.
//   Segment summary: carry_out = A*x + B, loss_seg(x) = sdd - 2x*sAd + x^2*sAA.
// Grid barrier (1024 blocks co-resident: regs<=64, smem 31KB -> 7 blocks/SM).
// Phase 2: first 256 blocks chain segments from L2, reduce, finalize.
//
// Inputs (metadata order):
//   0: Q [B,T,D]  1: expected_target_Q [B,T,D]  2: target_Q [B,T,D]
//   3: rewards [B,T,D]  4: target_policy_probs [B,T,D]  5: behaviour_policy_probs [B,T]
// Output: scalar fp32 = mean((Q[:, :-1] - q_ret)^2)

#define T_DIM 512
#define D_DIM 16
#define GAMMA 0.99f
#define BLOCK 128
#define SEG 4
#define SEGLEN 128                      // 511 = 4*128 - 1 (segment 3: 127 steps)
#define CH 4                            // steps per chunk
#define NCHUNK (SEGLEN / CH)            // 32
#define NCHAINS (2048 * 16)             // 32768
#define NBLK ((NCHAINS * SEG) / BLOCK)  // 1024 blocks, single co-resident wave
#define NBLK2 (NCHAINS / BLOCK)         // 256 combine blocks

// Stage layout (float words), per warp:
//   array a at a*AS;  within array: t_rel*32 + bl*16 + d  (32 consecutive
//   words per (a,t) row -> conflict-free LDS, no padding).
//   BPP slab (2b x 4t) at BPPOFF.
#define AS     (CH * 32)                // 128 words per array
#define BPPOFF (5 * AS)                 // 640
#define SSZ    (BPPOFF + 8)             // 648 words = 2592 B (16B-aligned)
#define NSTAGE 3

__device__ float g_sAA[SEG * NCHAINS];
__device__ float g_sAd[SEG * NCHAINS];
__device__ float g_sdd[SEG * NCHAINS];
__device__ float g_A  [SEG * NCHAINS];
__device__ float g_B  [SEG * NCHAINS];
__device__ float g_x0 [NCHAINS];        // TQ[:, -1] stashed by phase 1
__device__ float g_partials[NBLK2];
// Monotonic counters: never reset -> safe across CUDA-graph replays.
__device__ unsigned int g_arrive;
__device__ unsigned int g_ticket;

#define CPA16(dst, src) \
    asm volatile("cp.async.cg.shared.global [%0], [%1], 16;\n" \
                 :: "r"(dst), "l"(src))
#define CPA4(dst, src) \
    asm volatile("cp.async.ca.shared.global [%0], [%1], 4;\n" \
                 :: "r"(dst), "l"(src))
#define CPA_COMMIT()  asm volatile("cp.async.commit_group;\n")
#define CPA_WAIT2()   asm volatile("cp.async.wait_group 2;\n")
#define CPA_WAIT1()   asm volatile("cp.async.wait_group 1;\n")
#define CPA_WAIT0()   asm volatile("cp.async.wait_group 0;\n")

__global__ __launch_bounds__(BLOCK, 7)   // regs <= 64; smem 31KB -> 7 blocks/SM
void retrace_fused(const float* __restrict__ Q,
                   const float* __restrict__ E,
                   const float* __restrict__ TQ,
                   const float* __restrict__ R,
                   const float* __restrict__ TPP,
                   const float* __restrict__ BPP,
                   float* __restrict__ out,
                   double inv_count)
{
    __shared__ float sm[4][NSTAGE * SSZ];    // 31104 B; phase 2 aliases into this

    const int w    = threadIdx.x >> 5;
    const int lane = threadIdx.x & 31;
    float* Swarp = sm[w];

    // ======================= Phase 1: segment summaries =======================
    {
        const int wid_g = blockIdx.x * 4 + w;          // global warp id
        const int cid0  = (wid_g * 32) & (NCHAINS - 1);
        const int s     = (wid_g * 32) >> 15;          // segment 0..3
        const int cid   = cid0 + lane;
        const int bl    = lane >> 4;                   // b within warp (0/1)
        const int d     = lane & 15;
        const int b0    = cid0 >> 4;                   // warp covers b0, b0+1

        const int hi = (s == SEG - 1) ? (T_DIM - 2) : (s * SEGLEN + SEGLEN - 1);
        const int n  = (s == SEG - 1) ? (SEGLEN - 1) : SEGLEN;

        if (s == SEG - 1)
            g_x0[cid] = TQ[(b0 + bl) * (T_DIM * D_DIM) + (T_DIM - 1) * D_DIM + d];

        const unsigned sbase = (unsigned)__cvta_generic_to_shared(Swarp);
        const int half = lane >> 4;                    // loader role: b-row
        const int l16  = lane & 15;
        const int grow = (b0 + half) * (T_DIM * D_DIM);
        const int brow = (b0 + half) * T_DIM;
        // dst word offset of this lane's 16B within an array slab:
        const int doff = (l16 >> 2) * 32 + half * 16 + (l16 & 3) * 4;

        // Issue all cp.async for chunk topped at t=tc into stage `stg`.
#define ISSUE(tc, stg)                                                         \
        {                                                                      \
            const int orq = ((tc) - 3) * D_DIM + l16 * 4;   /* R/Q rows   */   \
            const int oe  = ((tc) - 2) * D_DIM + l16 * 4;   /* E/TQ/TPP   */   \
            const unsigned dstS = sbase + (unsigned)((stg) * (SSZ * 4));       \
            const unsigned dst0 = dstS + (unsigned)(doff * 4);                 \
            CPA16(dst0 + 0u * (AS * 4), R   + grow + orq);                     \
            CPA16(dst0 + 1u * (AS * 4), Q   + grow + orq);                     \
            CPA16(dst0 + 2u * (AS * 4), E   + grow + oe);                      \
            CPA16(dst0 + 3u * (AS * 4), TQ  + grow + oe);                      \
            CPA16(dst0 + 4u * (AS * 4), TPP + grow + oe);                      \
            if (l16 < 4)                                                       \
                CPA4(dstS + (unsigned)((BPPOFF + half * 4 + l16) * 4),         \
                     BPP + brow + ((tc) - 2) + l16);                           \
            CPA_COMMIT();                                                      \
        }

        float A = 1.0f, Bv = 0.0f;
        float sAA = 0.0f, sAd = 0.0f, sdd = 0.0f;

        ISSUE(hi,          0);                        // chunk 0 -> stage 0
        ISSUE(hi - CH,     1);                        // chunk 1 -> stage 1
        ISSUE(hi - 2 * CH, 2);                        // chunk 2 -> stage 2

        int stg = 0;                                  // stage of current chunk
        for (int c = 0; c < NCHUNK; ++c) {
            if (c < NCHUNK - 2)      { CPA_WAIT2(); } // chunk c complete
            else if (c == NCHUNK - 2){ CPA_WAIT1(); }
            else                     { CPA_WAIT0(); }
            __syncwarp();                             // cross-lane visibility

            // Compute chunk c from its stage (steps descend: tr = 3-k).
            const float* St = Swarp + stg * SSZ;
            const int steps = (n - CH * c < CH) ? (n - CH * c) : CH;
            #pragma unroll
            for (int k = 0; k < CH; ++k) {
                if (k >= steps) break;
                const int off = (3 - k) * 32 + bl * 16 + d;
                float r  = St[0 * AS + off];
                float qv = St[1 * AS + off];
                float e  = St[2 * AS + off];
                float tq = St[3 * AS + off];
                float tp = St[4 * AS + off];
                float bp = St[BPPOFF + bl * 4 + (3 - k)];

                float cc = __expf(fminf(tp - bp, 0.0f));
                float m  = GAMMA * cc;
                float t1 = fmaf(GAMMA, e, r);         // r + g*e
                Bv = fmaf(m, Bv - tq, t1);            // B' = m*(B - tq) + t1
                A  = m * A;                           // A' = m*A
                float dv = qv - Bv;                   // df = dv - A'*x
                sdd = fmaf(dv, dv, sdd);
                sAd = fmaf(A, dv, sAd);
                sAA = fmaf(A, A, sAA);
            }
            __syncwarp();                             // reads done before overwrite

            if (c + 3 < NCHUNK)
                ISSUE(hi - CH * (c + 3), stg);        // refill stage just freed
            stg = (stg == NSTAGE - 1) ? 0 : stg + 1;
        }
#undef ISSUE

        const int idx = s * NCHAINS + cid;
        g_sAA[idx] = sAA;
        g_sAd[idx] = sAd;
        g_sdd[idx] = sdd;
        g_A[idx]   = A;
        g_B[idx]   = Bv;
    }

    // ===================== Grid barrier (monotonic counter) ===================
    __threadfence();                                  // publish phase-1 writes
    __shared__ unsigned int s_target;
    __syncthreads();
    if (threadIdx.x == 0) {
        unsigned int t = atomicAdd(&g_arrive, 1u);
        s_target = (t / NBLK + 1u) * NBLK;            // end-count for THIS launch
    }
    __syncthreads();

    if (blockIdx.x >= NBLK2)                          // non-combine blocks exit
        return;                                       // (frees slots -> no deadlock)

    if (threadIdx.x == 0) {
        while (*(volatile unsigned int*)&g_arrive < s_target) { }
    }
    __syncthreads();
    __threadfence();                                  // acquire phase-1 writes

    // ================= Phase 2: chain segments, reduce, finalize ==============
    const int cid = blockIdx.x * BLOCK + threadIdx.x;

    float aa[SEG], ad[SEG], dd[SEG], Av[SEG], Bs[SEG];
    #pragma unroll
    for (int s = 0; s < SEG; ++s) {
        const int idx = s * NCHAINS + cid;
        aa[s] = g_sAA[idx];
        ad[s] = g_sAd[idx];
        dd[s] = g_sdd[idx];
        Av[s] = g_A[idx];
        Bs[s] = g_B[idx];
    }
    float x = g_x0[cid];

    float loss = 0.0f;
    #pragma unroll
    for (int s = SEG - 1; s >= 0; --s) {              // latest times first
        loss += fmaf(x, fmaf(x, aa[s], -2.0f * ad[s]), dd[s]);
        x = fmaf(Av[s], x, Bs[s]);
    }

    // Deterministic block reduction. Scratch aliased into phase-1 SMEM
    // (safe: past the grid barrier + __syncthreads below order all uses).
    float*  s_warp = (float*)&sm[0][0];               // 4 floats
    double* s_d    = (double*)&sm[1][0];              // 128 doubles

    #pragma unroll
    for (int off = 16; off > 0; off >>= 1)
        loss += __shfl_xor_sync(0xFFFFFFFFu, loss, off);

    __syncthreads();                                  // phase-1 smem reads done
    if ((threadIdx.x & 31) == 0) s_warp[threadIdx.x >> 5] = loss;
    __syncthreads();

    __shared__ bool s_last;
    if (threadIdx.x == 0) {
        g_partials[blockIdx.x] = s_warp[0] + s_warp[1] + s_warp[2] + s_warp[3];
        __threadfence();
        unsigned int t = atomicAdd(&g_ticket, 1u);
        s_last = ((t % NBLK2) == NBLK2 - 1);          // monotonic across replays
    }
    __syncthreads();

    if (s_last) {
        double v = 0.0;
        for (int i = threadIdx.x; i < NBLK2; i += BLOCK)
            v += (double)g_partials[i];
        s_d[threadIdx.x] = v;
        __syncthreads();
        for (int stride = BLOCK >> 1; stride > 0; stride >>= 1) {
            if (threadIdx.x < stride) s_d[threadIdx.x] += s_d[threadIdx.x + stride];
            __syncthreads();
        }
        if (threadIdx.x == 0)
            out[0] = (float)(s_d[0] * inv_count);
    }
}

extern "C" void kernel_launch(void* const* d_in, const int* in_sizes, int n_in,
                              void* d_out, int out_size)
{
    const float* Q   = (const float*)d_in[0];
    const float* E   = (const float*)d_in[1];
    const float* TQ  = (const float*)d_in[2];
    const float* R   = (const float*)d_in[3];
    const float* TPP = (const float*)d_in[4];
    const float* BPP = (const float*)d_in[5];

    const int B = in_sizes[5] / T_DIM;                // 2048
    const double inv_count =
        1.0 / ((double)B * (double)(T_DIM - 1) * (double)D_DIM);

    retrace_fused<<<NBLK, BLOCK>>>(Q, E, TQ, R, TPP, BPP,
                                   (float*)d_out, inv_count);
}

// round 16
// speedup vs baseline: 1.0667x; 1.0667x over previous
#include <cuda_runtime.h>

// Retrace: B=2048, T=512, D=16 (fp32). Single persistent kernel.
// Phase 1: warp-cooperative cp.async-staged segmented affine scan.
//   Each warp owns 32 chains (2 b-rows x 16 d) over one 256-step segment.
//   Per 8-step chunk: 5 arrays arrive as dense warp requests via cp.async.cg
//   (10x 16B per lane), BPP via cp.async.ca 4B. TWO SMEM stages, layout
//   [array][t][b*d] (conflict-free, zero padding). Per-step pipeline
//   overhead is half of the CH=4 variant.
//   Segment summary: carry_out = A*x + B, loss_seg(x) = sdd - 2x*sAd + x^2*sAA.
// Grid barrier (512 blocks co-resident: 5 blocks/SM x 148 = 740 >= 512).
// Phase 2: first 256 blocks chain 2 segments from L2, reduce, finalize.
//
// Inputs (metadata order):
//   0: Q [B,T,D]  1: expected_target_Q [B,T,D]  2: target_Q [B,T,D]
//   3: rewards [B,T,D]  4: target_policy_probs [B,T,D]  5: behaviour_policy_probs [B,T]
// Output: scalar fp32 = mean((Q[:, :-1] - q_ret)^2)

#define T_DIM 512
#define D_DIM 16
#define GAMMA 0.99f
#define BLOCK 128
#define SEG 2
#define SEGLEN 256                      // 511 = 2*256 - 1 (segment 1: 255 steps)
#define CH 8                            // steps per chunk
#define NCHUNK (SEGLEN / CH)            // 32
#define NCHAINS (2048 * 16)             // 32768
#define NBLK ((NCHAINS * SEG) / BLOCK)  // 512 blocks, single co-resident wave
#define NBLK2 (NCHAINS / BLOCK)         // 256 combine blocks

// Stage layout (float words), per warp:
//   array a at a*AS;  within array: t_rel*32 + bl*16 + d  (32 consecutive
//   words per (a,t) row -> conflict-free LDS, no padding).
//   BPP slab (2b x 8t) at BPPOFF.
#define AS     (CH * 32)                // 256 words per array
#define BPPOFF (5 * AS)                 // 1280
#define SSZ    (BPPOFF + 16)            // 1296 words = 5184 B (16B-aligned)
#define NSTAGE 2

__device__ float g_sAA[SEG * NCHAINS];
__device__ float g_sAd[SEG * NCHAINS];
__device__ float g_sdd[SEG * NCHAINS];
__device__ float g_A  [SEG * NCHAINS];
__device__ float g_B  [SEG * NCHAINS];
__device__ float g_x0 [NCHAINS];        // TQ[:, -1] stashed by phase 1
__device__ float g_partials[NBLK2];
// Monotonic counters: never reset -> safe across CUDA-graph replays.
__device__ unsigned int g_arrive;
__device__ unsigned int g_ticket;

#define CPA16(dst, src) \
    asm volatile("cp.async.cg.shared.global [%0], [%1], 16;\n" \
                 :: "r"(dst), "l"(src))
#define CPA4(dst, src) \
    asm volatile("cp.async.ca.shared.global [%0], [%1], 4;\n" \
                 :: "r"(dst), "l"(src))
#define CPA_COMMIT()  asm volatile("cp.async.commit_group;\n")
#define CPA_WAIT1()   asm volatile("cp.async.wait_group 1;\n")
#define CPA_WAIT0()   asm volatile("cp.async.wait_group 0;\n")

__global__ __launch_bounds__(BLOCK, 5)   // smem 41.5KB -> 5 blocks/SM; regs free
void retrace_fused(const float* __restrict__ Q,
                   const float* __restrict__ E,
                   const float* __restrict__ TQ,
                   const float* __restrict__ R,
                   const float* __restrict__ TPP,
                   const float* __restrict__ BPP,
                   float* __restrict__ out,
                   double inv_count)
{
    __shared__ float sm[4][NSTAGE * SSZ];    // 41472 B; phase 2 aliases into this

    const int w    = threadIdx.x >> 5;
    const int lane = threadIdx.x & 31;
    float* Swarp = sm[w];

    // ======================= Phase 1: segment summaries =======================
    {
        const int wid_g = blockIdx.x * 4 + w;          // global warp id
        const int cid0  = (wid_g * 32) & (NCHAINS - 1);
        const int s     = (wid_g * 32) >> 15;          // segment 0..1
        const int cid   = cid0 + lane;
        const int bl    = lane >> 4;                   // b within warp (0/1)
        const int d     = lane & 15;
        const int b0    = cid0 >> 4;                   // warp covers b0, b0+1

        const int hi = (s == SEG - 1) ? (T_DIM - 2) : (s * SEGLEN + SEGLEN - 1);
        const int n  = (s == SEG - 1) ? (SEGLEN - 1) : SEGLEN;

        if (s == SEG - 1)
            g_x0[cid] = TQ[(b0 + bl) * (T_DIM * D_DIM) + (T_DIM - 1) * D_DIM + d];

        const unsigned sbase = (unsigned)__cvta_generic_to_shared(Swarp);
        const int half = lane >> 4;                    // loader role: b-row
        const int l16  = lane & 15;
        const int grow = (b0 + half) * (T_DIM * D_DIM);
        const int brow = (b0 + half) * T_DIM;
        // Loader geometry: l16 -> (row-within-4, 4-float column). Two passes
        // per array cover 8 rows. Word offsets:
        const int srcoff = (l16 >> 2) * D_DIM + (l16 & 3) * 4;       // in gmem row block
        const int doff   = (l16 >> 2) * 32 + half * 16 + (l16 & 3) * 4; // in smem slab

        // Issue all cp.async for chunk topped at t=tc into stage `stg`.
        // R/Q rows tc-7..tc ; E/TQ/TPP rows tc-6..tc+1 ; BPP tc-6..tc+1.
#define ISSUE(tc, stg)                                                         \
        {                                                                      \
            const int o0 = ((tc) - 7) * D_DIM + srcoff;   /* R/Q pass0 */      \
            const int o1 = o0 + 4 * D_DIM;                /* R/Q pass1 */      \
            const int e0 = o0 + D_DIM;                    /* E/TQ/TPP  */      \
            const int e1 = e0 + 4 * D_DIM;                                     \
            const unsigned dstS = sbase + (unsigned)((stg) * (SSZ * 4));       \
            const unsigned dA   = dstS + (unsigned)(doff * 4);                 \
            CPA16(dA + 0u * (AS * 4),        R   + grow + o0);                 \
            CPA16(dA + 0u * (AS * 4) + 512u, R   + grow + o1);                 \
            CPA16(dA + 1u * (AS * 4),        Q   + grow + o0);                 \
            CPA16(dA + 1u * (AS * 4) + 512u, Q   + grow + o1);                 \
            CPA16(dA + 2u * (AS * 4),        E   + grow + e0);                 \
            CPA16(dA + 2u * (AS * 4) + 512u, E   + grow + e1);                 \
            CPA16(dA + 3u * (AS * 4),        TQ  + grow + e0);                 \
            CPA16(dA + 3u * (AS * 4) + 512u, TQ  + grow + e1);                 \
            CPA16(dA + 4u * (AS * 4),        TPP + grow + e0);                 \
            CPA16(dA + 4u * (AS * 4) + 512u, TPP + grow + e1);                 \
            if (l16 < 8)                                                       \
                CPA4(dstS + (unsigned)((BPPOFF + half * 8 + l16) * 4),         \
                     BPP + brow + ((tc) - 6) + l16);                           \
            CPA_COMMIT();                                                      \
        }

        float A = 1.0f, Bv = 0.0f;
        float sAA = 0.0f, sAd = 0.0f, sdd = 0.0f;

        ISSUE(hi,      0);                            // chunk 0 -> stage 0
        ISSUE(hi - CH, 1);                            // chunk 1 -> stage 1

        for (int c = 0; c < NCHUNK; ++c) {
            if (c < NCHUNK - 1) { CPA_WAIT1(); } else { CPA_WAIT0(); }
            __syncwarp();                             // cross-lane visibility

            // Compute chunk c from its stage (steps descend: trel = 7-k).
            const float* St = Swarp + (c & 1) * SSZ;
            const int steps = (n - CH * c < CH) ? (n - CH * c) : CH;
            #pragma unroll
            for (int k = 0; k < CH; ++k) {
                if (k >= steps) break;
                const int off = (7 - k) * 32 + bl * 16 + d;
                float r  = St[0 * AS + off];
                float qv = St[1 * AS + off];
                float e  = St[2 * AS + off];
                float tq = St[3 * AS + off];
                float tp = St[4 * AS + off];
                float bp = St[BPPOFF + bl * 8 + (7 - k)];

                float cc = __expf(fminf(tp - bp, 0.0f));
                float m  = GAMMA * cc;
                float t1 = fmaf(GAMMA, e, r);         // r + g*e
                Bv = fmaf(m, Bv - tq, t1);            // B' = m*(B - tq) + t1
                A  = m * A;                           // A' = m*A
                float dv = qv - Bv;                   // df = dv - A'*x
                sdd = fmaf(dv, dv, sdd);
                sAd = fmaf(A, dv, sAd);
                sAA = fmaf(A, A, sAA);
            }
            __syncwarp();                             // reads done before overwrite

            if (c + 2 < NCHUNK)
                ISSUE(hi - CH * (c + 2), c & 1);      // refill the stage just freed
        }
#undef ISSUE

        const int idx = s * NCHAINS + cid;
        g_sAA[idx] = sAA;
        g_sAd[idx] = sAd;
        g_sdd[idx] = sdd;
        g_A[idx]   = A;
        g_B[idx]   = Bv;
    }

    // ===================== Grid barrier (monotonic counter) ===================
    __threadfence();                                  // publish phase-1 writes
    __shared__ unsigned int s_target;
    __syncthreads();
    if (threadIdx.x == 0) {
        unsigned int t = atomicAdd(&g_arrive, 1u);
        s_target = (t / NBLK + 1u) * NBLK;            // end-count for THIS launch
    }
    __syncthreads();

    if (blockIdx.x >= NBLK2)                          // non-combine blocks exit
        return;                                       // (frees slots -> no deadlock)

    if (threadIdx.x == 0) {
        while (*(volatile unsigned int*)&g_arrive < s_target) { }
    }
    __syncthreads();
    __threadfence();                                  // acquire phase-1 writes

    // ================= Phase 2: chain segments, reduce, finalize ==============
    const int cid = blockIdx.x * BLOCK + threadIdx.x;

    float aa[SEG], ad[SEG], dd[SEG], Av[SEG], Bs[SEG];
    #pragma unroll
    for (int s = 0; s < SEG; ++s) {
        const int idx = s * NCHAINS + cid;
        aa[s] = g_sAA[idx];
        ad[s] = g_sAd[idx];
        dd[s] = g_sdd[idx];
        Av[s] = g_A[idx];
        Bs[s] = g_B[idx];
    }
    float x = g_x0[cid];

    float loss = 0.0f;
    #pragma unroll
    for (int s = SEG - 1; s >= 0; --s) {              // latest times first
        loss += fmaf(x, fmaf(x, aa[s], -2.0f * ad[s]), dd[s]);
        x = fmaf(Av[s], x, Bs[s]);
    }

    // Deterministic block reduction. Scratch aliased into phase-1 SMEM
    // (safe: past the grid barrier + __syncthreads below order all uses).
    float*  s_warp = (float*)&sm[0][0];               // 4 floats
    double* s_d    = (double*)&sm[1][0];              // 128 doubles

    #pragma unroll
    for (int off = 16; off > 0; off >>= 1)
        loss += __shfl_xor_sync(0xFFFFFFFFu, loss, off);

    __syncthreads();                                  // phase-1 smem reads done
    if ((threadIdx.x & 31) == 0) s_warp[threadIdx.x >> 5] = loss;
    __syncthreads();

    __shared__ bool s_last;
    if (threadIdx.x == 0) {
        g_partials[blockIdx.x] = s_warp[0] + s_warp[1] + s_warp[2] + s_warp[3];
        __threadfence();
        unsigned int t = atomicAdd(&g_ticket, 1u);
        s_last = ((t % NBLK2) == NBLK2 - 1);          // monotonic across replays
    }
    __syncthreads();

    if (s_last) {
        double v = 0.0;
        for (int i = threadIdx.x; i < NBLK2; i += BLOCK)
            v += (double)g_partials[i];
        s_d[threadIdx.x] = v;
        __syncthreads();
        for (int stride = BLOCK >> 1; stride > 0; stride >>= 1) {
            if (threadIdx.x < stride) s_d[threadIdx.x] += s_d[threadIdx.x + stride];
            __syncthreads();
        }
        if (threadIdx.x == 0)
            out[0] = (float)(s_d[0] * inv_count);
    }
}

extern "C" void kernel_launch(void* const* d_in, const int* in_sizes, int n_in,
                              void* d_out, int out_size)
{
    const float* Q   = (const float*)d_in[0];
    const float* E   = (const float*)d_in[1];
    const float* TQ  = (const float*)d_in[2];
    const float* R   = (const float*)d_in[3];
    const float* TPP = (const float*)d_in[4];
    const float* BPP = (const float*)d_in[5];

    const int B = in_sizes[5] / T_DIM;                // 2048
    const double inv_count =
        1.0 / ((double)B * (double)(T_DIM - 1) * (double)D_DIM);

    retrace_fused<<<NBLK, BLOCK>>>(Q, E, TQ, R, TPP, BPP,
                                   (float*)d_out, inv_count);
}